// round 3
// baseline (speedup 1.0000x reference)
#include <cuda_runtime.h>
#include <math.h>

// Problem constants
#define BSZ   1024
#define KDIM  256
#define NPTS  128
#define LOG2PI_F 1.8378770664093453f
#define LOG1P_HALF 0.40546510810816438f

// Output layout offsets
#define OFF_SAMPLED 0
#define OFF_GEN     524288
#define OFF_REAL    655360
#define OFF_LOSSA   786432
#define OFF_LOSSB   917504

// GEMM tiling: 32x32 tile, 128 threads, micro 2(m) x 4(n), full-K smem
#define BM 32
#define BN 32
#define AS_LD 260          // 256 + 4 pad (keeps 16B align, breaks bank alignment)
#define WS_LD 258          // 256 + 2 pad (8B align for LDS.64, bank shift 2)
#define SMEM_WORDS (BM * AS_LD + BN * WS_LD)
#define SMEM_BYTES (SMEM_WORDS * 4)

typedef unsigned long long ull;

// Scratch (device globals: no allocation allowed)
__device__ float g_bufA[BSZ * KDIM];
__device__ float g_bufB[BSZ * KDIM];
__device__ float g_mu[BSZ * KDIM];     // (B, N, 2) flattened
__device__ float g_WpT[KDIM * 256];    // Wp transposed to [H][n*2+k]

__device__ __forceinline__ void ffma2(ull& d, ull a, ull b) {
    asm("fma.rn.f32x2 %0, %1, %2, %0;" : "+l"(d) : "l"(a), "l"(b));
}
__device__ __forceinline__ float pair_sum(ull v) {
    union { ull u; float f[2]; } c; c.u = v;
    return c.f[0] + c.f[1];
}

// ---------------------------------------------------------------------------
// Transpose Wp (N,H,2) -> WpT[h][n*2+k]
// ---------------------------------------------------------------------------
__global__ __launch_bounds__(256) void transpose_wp_kernel(const float* __restrict__ Wp,
                                                           float* __restrict__ WpT) {
    int idx = blockIdx.x * 256 + threadIdx.x;   // 0..65535
    int h = idx >> 8;
    int col = idx & 255;                        // col = n*2 + k
    WpT[idx] = Wp[(col >> 1) * 512 + h * 2 + (col & 1)];
}

// ---------------------------------------------------------------------------
// fp32 GEMM with packed f32x2 FMA: C[1024,256] = act(A @ W + bias + addc)
// A row-major in smem; W transposed to [n][k] in smem; reduction paired on k.
// Grid (256/32, 1024/32) = (8, 32) = 256 CTAs, 128 threads.
// ---------------------------------------------------------------------------
__global__ __launch_bounds__(128) void gemm_kernel(
    const float* __restrict__ A, const float* __restrict__ W,
    const float* __restrict__ bias, float* __restrict__ C,
    int doRelu, float addc)
{
    extern __shared__ float smem[];
    float* As  = smem;                 // [BM][AS_LD], row-major in k
    float* Wst = smem + BM * AS_LD;    // [BN][WS_LD], n-major rows, k contiguous

    const int t  = threadIdx.x;
    const int m0 = blockIdx.y * BM;
    const int n0 = blockIdx.x * BN;

    // ---- prologue: coalesced loads ----
    // As: 32 rows x 64 float4 = 2048 float4
#pragma unroll
    for (int it = 0; it < 16; it++) {
        int idx = it * 128 + t;
        int r = idx >> 6, q = idx & 63;
        float4 v = *(const float4*)&A[(m0 + r) * KDIM + q * 4];
        *(float4*)&As[r * AS_LD + q * 4] = v;
    }
    // Wst: transpose W[k][n0+..] -> Wst[n][k]; 256 k x 8 float4 = 2048 float4
#pragma unroll
    for (int it = 0; it < 16; it++) {
        int idx = it * 128 + t;
        int k = idx >> 3, q = idx & 7;
        float4 v = *(const float4*)&W[k * 256 + n0 + q * 4];
        Wst[(q * 4 + 0) * WS_LD + k] = v.x;
        Wst[(q * 4 + 1) * WS_LD + k] = v.y;
        Wst[(q * 4 + 2) * WS_LD + k] = v.z;
        Wst[(q * 4 + 3) * WS_LD + k] = v.w;
    }
    __syncthreads();

    const int tx = t & 7;      // 0..7  -> cols 4*tx .. 4*tx+3
    const int ty = t >> 3;     // 0..15 -> rows 2*ty, 2*ty+1

    const float* aBase = &As[(2 * ty) * AS_LD];
    const float* bBase = &Wst[(4 * tx) * WS_LD];

    ull acc[2][4];
#pragma unroll
    for (int i = 0; i < 2; i++)
#pragma unroll
        for (int j = 0; j < 4; j++) acc[i][j] = 0ull;

#pragma unroll 8
    for (int kp = 0; kp < KDIM / 2; kp++) {
        const int k = 2 * kp;
        ull A0 = *(const ull*)(aBase + k);
        ull A1 = *(const ull*)(aBase + AS_LD + k);
        ull B0 = *(const ull*)(bBase + k);
        ull B1 = *(const ull*)(bBase + WS_LD + k);
        ull B2 = *(const ull*)(bBase + 2 * WS_LD + k);
        ull B3 = *(const ull*)(bBase + 3 * WS_LD + k);
        ffma2(acc[0][0], A0, B0);
        ffma2(acc[0][1], A0, B1);
        ffma2(acc[0][2], A0, B2);
        ffma2(acc[0][3], A0, B3);
        ffma2(acc[1][0], A1, B0);
        ffma2(acc[1][1], A1, B1);
        ffma2(acc[1][2], A1, B2);
        ffma2(acc[1][3], A1, B3);
    }

    // ---- epilogue ----
    float4 bv = *(const float4*)&bias[n0 + tx * 4];
    float bb[4] = {bv.x + addc, bv.y + addc, bv.z + addc, bv.w + addc};
#pragma unroll
    for (int i = 0; i < 2; i++) {
        float4 v;
        v.x = pair_sum(acc[i][0]) + bb[0];
        v.y = pair_sum(acc[i][1]) + bb[1];
        v.z = pair_sum(acc[i][2]) + bb[2];
        v.w = pair_sum(acc[i][3]) + bb[3];
        if (doRelu) {
            v.x = fmaxf(v.x, 0.0f); v.y = fmaxf(v.y, 0.0f);
            v.z = fmaxf(v.z, 0.0f); v.w = fmaxf(v.w, 0.0f);
        }
        *(float4*)&C[(m0 + 2 * ty + i) * 256 + n0 + tx * 4] = v;
    }
}

// ---------------------------------------------------------------------------
// Fused tail: one CTA per batch row b; thread = (n, s), tid = 2n + s.
// ---------------------------------------------------------------------------
__global__ __launch_bounds__(256) void tail_kernel(
    const float* __restrict__ realPoints,
    const float* __restrict__ predMu,
    const float* __restrict__ predScale,
    const float* __restrict__ eps,
    float* __restrict__ out)
{
    const int b = blockIdx.x;
    __shared__ float mu_s[256];      // (n,k)
    __shared__ float am[128];        // -0.5/dev_m^2
    __shared__ float cm[128];        // -2*log(dev_m) - LOG2PI
    __shared__ float sc[7];

    const int tid = threadIdx.x;
    mu_s[tid] = g_mu[b * 256 + tid];
    if (tid < 128) {
        float dev = 0.001f + (float)tid * (0.009f / 127.0f);
        am[tid] = -0.5f / (dev * dev);
        cm[tid] = -2.0f * logf(dev) - LOG2PI_F;
    }
    if (tid == 0) {
        sc[0] = realPoints[b * 2];
        sc[1] = realPoints[b * 2 + 1];
        sc[2] = predMu[b * 2];
        sc[3] = predMu[b * 2 + 1];
        float p0 = predScale[b * 2], p1 = predScale[b * 2 + 1];
        sc[4] = 1.0f / p0;
        sc[5] = 1.0f / p1;
        sc[6] = logf(p0) + logf(p1);
    }
    __syncthreads();

    const int n = tid >> 1;
    const int s = tid & 1;

    const float mu0 = mu_s[2 * n];
    const float mu1 = mu_s[2 * n + 1];
    const float dev = 0.001f + (float)n * (0.009f / 127.0f);

    const int eoff = s * (BSZ * NPTS * 2) + (b * NPTS + n) * 2;
    const float e0 = eps[eoff];
    const float e1 = eps[eoff + 1];
    const float s0 = fmaf(dev, e0, mu0);
    const float s1 = fmaf(dev, e1, mu1);

    {
        long so = ((long)(s * NPTS + n) * BSZ + b) * 2;
        out[OFF_SAMPLED + so]     = s0;
        out[OFF_SAMPLED + so + 1] = s1;
    }

    // lossB: softmax over m, pick diag m=n
    float sumexp = 0.0f;
    float en = 0.0f;
#pragma unroll 4
    for (int m = 0; m < 128; m++) {
        float d0 = s0 - mu_s[2 * m];
        float d1 = s1 - mu_s[2 * m + 1];
        float ss = fmaf(d0, d0, d1 * d1);
        float lb = fmaf(ss, am[m], cm[m]);
        float e  = __expf(lb);
        sumexp += e;
        if (m == n) en = e;
    }
    float diag = en / sumexp;
    float lbv  = 1.0f - diag;
    out[OFF_LOSSB + b * 256 + tid] = lbv * lbv;

    float z0 = (s0 - sc[2]) * sc[4];
    float z1 = (s1 - sc[3]) * sc[5];
    float lp = fmaf(-0.5f, fmaf(z0, z0, z1 * z1), -sc[6] - LOG2PI_F);
    float gl  = 1.0f / (1.0f + __expf(-lp));
    float sgn = 1.0f / (1.0f + __expf(lp));
    float tA  = LOG1P_HALF - log1pf(sgn);
    tA *= tA;

    float gl_o = __shfl_xor_sync(0xffffffffu, gl, 1);
    float tA_o = __shfl_xor_sync(0xffffffffu, tA, 1);

    if (s == 0) {
        float glm   = 0.5f * (gl + gl_o);
        float lossA = 0.5f * (tA + tA_o);
        float dr0 = sc[0] - mu0;
        float dr1 = sc[1] - mu1;
        float ssr = fmaf(dr0, dr0, dr1 * dr1);
        float rlp = fmaf(ssr, am[n], cm[n]);
        float rl  = 1.0f / (1.0f + __expf(-rlp));
        out[OFF_REAL  + b * NPTS + n] = rl;
        out[OFF_LOSSA + b * NPTS + n] = lossA;
        out[OFF_GEN   + b * NPTS + n] = glm * (1.0f - rl);
    }
}

// ---------------------------------------------------------------------------
extern "C" void kernel_launch(void* const* d_in, const int* in_sizes, int n_in,
                              void* d_out, int out_size) {
    const float* latents    = (const float*)d_in[0];
    const float* realPoints = (const float*)d_in[1];
    const float* predMu     = (const float*)d_in[2];
    const float* predScale  = (const float*)d_in[3];
    const float* eps        = (const float*)d_in[4];
    const float* W[5]  = {(const float*)d_in[5],  (const float*)d_in[7],
                          (const float*)d_in[9],  (const float*)d_in[11],
                          (const float*)d_in[13]};
    const float* bb[5] = {(const float*)d_in[6],  (const float*)d_in[8],
                          (const float*)d_in[10], (const float*)d_in[12],
                          (const float*)d_in[14]};
    const float* Wp = (const float*)d_in[15];
    const float* bp = (const float*)d_in[16];
    float* out = (float*)d_out;

    float *bufA, *bufB, *mu, *WpT;
    cudaGetSymbolAddress((void**)&bufA, g_bufA);
    cudaGetSymbolAddress((void**)&bufB, g_bufB);
    cudaGetSymbolAddress((void**)&mu,   g_mu);
    cudaGetSymbolAddress((void**)&WpT,  g_WpT);

    cudaFuncSetAttribute(gemm_kernel,
                         cudaFuncAttributeMaxDynamicSharedMemorySize, SMEM_BYTES);

    transpose_wp_kernel<<<256, 256>>>(Wp, WpT);

    dim3 ggrid(KDIM / BN, BSZ / BM);   // (8, 32) = 256 CTAs
    gemm_kernel<<<ggrid, 128, SMEM_BYTES>>>(latents, W[0], bb[0], bufA, 1, 0.0f);
    gemm_kernel<<<ggrid, 128, SMEM_BYTES>>>(bufA,    W[1], bb[1], bufB, 1, 0.0f);
    gemm_kernel<<<ggrid, 128, SMEM_BYTES>>>(bufB,    W[2], bb[2], bufA, 1, 0.0f);
    gemm_kernel<<<ggrid, 128, SMEM_BYTES>>>(bufA,    W[3], bb[3], bufB, 1, 0.0f);
    gemm_kernel<<<ggrid, 128, SMEM_BYTES>>>(bufB,    W[4], bb[4], bufA, 1, 0.0f);
    gemm_kernel<<<ggrid, 128, SMEM_BYTES>>>(bufA, WpT, bp, mu, 0, 0.5f);

    tail_kernel<<<BSZ, 256>>>(realPoints, predMu, predScale, eps, out);
}